// round 4
// baseline (speedup 1.0000x reference)
#include <cuda_runtime.h>
#include <cuda_bf16.h>
#include <cstdint>
#include <math.h>

#define N_OBJ   2048
#define N_REL   32768
#define FEAT    2048
#define DIM     512
#define NC_OBJ  151
#define NC_PRED 51

typedef unsigned short u16;

// ---------------- fp32 scratch ---------------------------------------------
__device__ __align__(128) float g_pfeatA[N_REL*DIM];
__device__ __align__(128) float g_pfeatB[N_REL*DIM];
__device__ __align__(128) float g_ofeatA[N_OBJ*DIM];
__device__ __align__(128) float g_ofeatB[N_OBJ*DIM];
__device__ __align__(128) float g_fco0  [N_OBJ*DIM];
__device__ __align__(128) float g_fco1  [N_OBJ*DIM];
__device__ __align__(128) float g_acc0  [N_OBJ*DIM];
__device__ __align__(128) float g_acc1  [N_OBJ*DIM];
__device__ __align__(128) float g_osA   [N_OBJ*NC_OBJ];
__device__ __align__(128) float g_osB   [N_OBJ*NC_OBJ];
__device__ __align__(128) float g_psA   [N_REL*NC_PRED];
__device__ __align__(128) float g_psB   [N_REL*NC_PRED];
__device__ __align__(128) float g_sacc0 [N_OBJ*NC_OBJ];
__device__ __align__(128) float g_sacc1 [N_OBJ*NC_OBJ];
__device__ __align__(128) float g_fcs0  [N_OBJ*NC_PRED];
__device__ __align__(128) float g_fcs1  [N_OBJ*NC_PRED];
__device__ __align__(128) float g_deg   [2*N_OBJ];

// ---------------- bf16 hi/lo split buffers ----------------------------------
__device__ __align__(128) u16 g_xo_h[N_OBJ*FEAT],  g_xo_l[N_OBJ*FEAT];
__device__ __align__(128) u16 g_xp_h[N_REL*FEAT],  g_xp_l[N_REL*FEAT];
__device__ __align__(128) u16 g_hob_h[N_OBJ*DIM],  g_hob_l[N_OBJ*DIM];
__device__ __align__(128) u16 g_hpr_h[N_REL*DIM],  g_hpr_l[N_REL*DIM];
__device__ __align__(128) u16 g_pf_h[N_REL*DIM],   g_pf_l[N_REL*DIM];
__device__ __align__(128) u16 g_of_h0[N_OBJ*DIM],  g_of_l0[N_OBJ*DIM];
__device__ __align__(128) u16 g_of_h1[N_OBJ*DIM],  g_of_l1[N_OBJ*DIM];
__device__ __align__(128) u16 g_oW1h[FEAT*DIM], g_oW1l[FEAT*DIM];
__device__ __align__(128) u16 g_oW2h[DIM*DIM],  g_oW2l[DIM*DIM];
__device__ __align__(128) u16 g_rW1h[FEAT*DIM], g_rW1l[FEAT*DIM];
__device__ __align__(128) u16 g_rW2h[DIM*DIM],  g_rW2l[DIM*DIM];
__device__ __align__(128) u16 g_Wcfh[4*DIM*DIM], g_Wcfl[4*DIM*DIM];

// ---------------- helpers ------------------------------------------------------
__device__ __forceinline__ uint32_t smem_u32(const void* p) {
    uint32_t a;
    asm("{ .reg .u64 t; cvta.to.shared.u64 t, %1; cvt.u32.u64 %0, t; }" : "=r"(a) : "l"(p));
    return a;
}
// pack {hi16=bf16(y), lo16=bf16(x)} -> memory order x then y
__device__ __forceinline__ uint32_t pack_bf16x2(float x, float y) {
    uint32_t d;
    asm("cvt.rn.bf16x2.f32 %0, %1, %2;" : "=r"(d) : "f"(y), "f"(x));
    return d;
}
__device__ __forceinline__ void split_pair(float x, float y, uint32_t& hi, uint32_t& lo) {
    hi = pack_bf16x2(x, y);
    float hx = __uint_as_float((hi & 0xffffu) << 16);
    float hy = __uint_as_float(hi & 0xffff0000u);
    lo = pack_bf16x2(x - hx, y - hy);
}
__device__ __forceinline__ void ldsm_x4(uint32_t* r, uint32_t addr) {
    asm volatile("ldmatrix.sync.aligned.m8n8.x4.shared.b16 {%0,%1,%2,%3}, [%4];"
                 : "=r"(r[0]), "=r"(r[1]), "=r"(r[2]), "=r"(r[3]) : "r"(addr));
}
__device__ __forceinline__ void ldsm_x4_t(uint32_t* r, uint32_t addr) {
    asm volatile("ldmatrix.sync.aligned.m8n8.x4.trans.shared.b16 {%0,%1,%2,%3}, [%4];"
                 : "=r"(r[0]), "=r"(r[1]), "=r"(r[2]), "=r"(r[3]) : "r"(addr));
}
__device__ __forceinline__ void mma16816(float* c, const uint32_t* a, uint32_t b0, uint32_t b1) {
    asm volatile("mma.sync.aligned.m16n8k16.row.col.f32.bf16.bf16.f32 "
                 "{%0,%1,%2,%3}, {%4,%5,%6,%7}, {%8,%9}, {%0,%1,%2,%3};"
                 : "+f"(c[0]), "+f"(c[1]), "+f"(c[2]), "+f"(c[3])
                 : "r"(a[0]), "r"(a[1]), "r"(a[2]), "r"(a[3]), "r"(b0), "r"(b1));
}
__device__ __forceinline__ void cp16(uint32_t dst, const void* src) {
    asm volatile("cp.async.cg.shared.global [%0], [%1], 16;" :: "r"(dst), "l"(src) : "memory");
}
#define CP_COMMIT() asm volatile("cp.async.commit_group;" ::: "memory")
#define CP_WAIT2()  asm volatile("cp.async.wait_group 2;" ::: "memory")

// ---------------- bf16-split tensor GEMM (preconverted inputs) ----------------
// C[M,N] = op(Ahi/lo[M,K] @ Bhi/lo[K,N] + bias); 3 mma passes (hh + hl + lh).
// M%128==0, N%128==0, K%32==0. Optional: f32 C, split outputs Ch/Cl, scatter sacc.
#define APITCH 80
#define BPITCH 272
#define ST_AHI 0
#define ST_ALO 10240
#define ST_BHI 20480
#define ST_BLO 29184
#define ST_SZ  37888
#define NSTAGE 4
#define SMEM_GEMM (NSTAGE*ST_SZ)

__global__ __launch_bounds__(256)
void gemm_bf16p(const u16* __restrict__ Ahi, const u16* __restrict__ Alo,
                const u16* __restrict__ Bhi, const u16* __restrict__ Blo,
                const float* __restrict__ bias, int M, int K, int N, int doRelu,
                float* __restrict__ C, u16* __restrict__ Ch, u16* __restrict__ Cl,
                const int* __restrict__ rel, int sel, float* __restrict__ sacc) {
    extern __shared__ __align__(128) char smem[];
    const uint32_t sb = smem_u32(smem);
    const int tid = threadIdx.x;
    const int lane = tid & 31;
    const int w = tid >> 5;
    const int warp_m = (w & 1) * 64;
    const int warp_n = (w >> 1) * 32;
    const int m0 = blockIdx.y * 128;
    const int n0 = blockIdx.x * 128;
    const int KT = K >> 5;

    float acc[16][4];
    #pragma unroll
    for (int i = 0; i < 16; i++)
        #pragma unroll
        for (int j = 0; j < 4; j++) acc[i][j] = 0.0f;

    auto issue = [&](int kt) {
        const uint32_t st = sb + (kt & 3) * ST_SZ;
        #pragma unroll
        for (int i = 0; i < 2; i++) {
            int idx = i * 256 + tid;
            int arow = idx >> 2, ac = idx & 3;
            size_t ga = (size_t)(m0 + arow) * K + kt * 32 + ac * 8;
            uint32_t ao = (uint32_t)(arow * APITCH + ac * 16);
            cp16(st + ST_AHI + ao, Ahi + ga);
            cp16(st + ST_ALO + ao, Alo + ga);
            int brow = idx >> 4, bc = idx & 15;
            size_t gb = (size_t)(kt * 32 + brow) * N + n0 + bc * 8;
            uint32_t bo = (uint32_t)(brow * BPITCH + bc * 16);
            cp16(st + ST_BHI + bo, Bhi + gb);
            cp16(st + ST_BLO + bo, Blo + gb);
        }
    };

    // prologue: 3 stages in flight
    issue(0); CP_COMMIT();
    issue(1); CP_COMMIT();
    issue(2); CP_COMMIT();

    for (int kt = 0; kt < KT; kt++) {
        CP_WAIT2();
        __syncthreads();
        if (kt + 3 < KT) issue(kt + 3);
        CP_COMMIT();

        const uint32_t st = sb + (kt & 3) * ST_SZ;
        #pragma unroll
        for (int ks = 0; ks < 2; ks++) {
            uint32_t ah[4][4], al[4][4];
            const uint32_t a_off = (uint32_t)((warp_m + (lane & 15)) * APITCH
                                              + ks * 32 + (lane >> 4) * 16);
            #pragma unroll
            for (int mi = 0; mi < 4; mi++) {
                ldsm_x4(ah[mi], st + ST_AHI + a_off + mi * 16 * APITCH);
                ldsm_x4(al[mi], st + ST_ALO + a_off + mi * 16 * APITCH);
            }
            const uint32_t b_off = (uint32_t)((ks * 16 + (lane & 15)) * BPITCH
                                              + (warp_n + (lane >> 4) * 8) * 2);
            #pragma unroll
            for (int np = 0; np < 2; np++) {
                uint32_t bh[4], bl[4];
                ldsm_x4_t(bh, st + ST_BHI + b_off + np * 32);
                ldsm_x4_t(bl, st + ST_BLO + b_off + np * 32);
                #pragma unroll
                for (int mi = 0; mi < 4; mi++) {
                    #pragma unroll
                    for (int j = 0; j < 2; j++) {
                        float* c = acc[mi * 4 + np * 2 + j];
                        mma16816(c, ah[mi], bh[2*j], bh[2*j+1]);
                        mma16816(c, ah[mi], bl[2*j], bl[2*j+1]);
                        mma16816(c, al[mi], bh[2*j], bh[2*j+1]);
                    }
                }
            }
        }
        __syncthreads();
    }

    // ---- epilogue ----
    const int g = lane >> 2, tig = lane & 3;
    #pragma unroll
    for (int mi = 0; mi < 4; mi++) {
        const int r0 = m0 + warp_m + mi * 16 + g;
        const int r1 = r0 + 8;
        int t0 = 0, t1 = 0;
        if (sacc) { t0 = rel[r0 * 2 + sel]; t1 = rel[r1 * 2 + sel]; }
        #pragma unroll
        for (int ni = 0; ni < 4; ni++) {
            const int c = n0 + warp_n + ni * 8 + tig * 2;
            float b0 = bias[c], b1 = bias[c + 1];
            float* a = acc[mi * 4 + ni];
            float v0 = a[0] + b0, v1 = a[1] + b1, v2 = a[2] + b0, v3 = a[3] + b1;
            if (doRelu) {
                v0 = fmaxf(v0, 0.0f); v1 = fmaxf(v1, 0.0f);
                v2 = fmaxf(v2, 0.0f); v3 = fmaxf(v3, 0.0f);
            }
            if (sacc) {
                atomicAdd(&sacc[(size_t)t0 * N + c],     v0);
                atomicAdd(&sacc[(size_t)t0 * N + c + 1], v1);
                atomicAdd(&sacc[(size_t)t1 * N + c],     v2);
                atomicAdd(&sacc[(size_t)t1 * N + c + 1], v3);
            } else {
                if (C) {
                    *(float2*)(C + (size_t)r0 * N + c) = make_float2(v0, v1);
                    *(float2*)(C + (size_t)r1 * N + c) = make_float2(v2, v3);
                }
                if (Ch) {
                    uint32_t h, l;
                    split_pair(v0, v1, h, l);
                    *(uint32_t*)(Ch + (size_t)r0 * N + c) = h;
                    *(uint32_t*)(Cl + (size_t)r0 * N + c) = l;
                    split_pair(v2, v3, h, l);
                    *(uint32_t*)(Ch + (size_t)r1 * N + c) = h;
                    *(uint32_t*)(Cl + (size_t)r1 * N + c) = l;
                }
            }
        }
    }
}

// ---------------- split (f32 -> bf16 hi/lo) converter, 4 elems/thread ---------
__global__ void split_kernel(const float* __restrict__ x, u16* __restrict__ hi,
                             u16* __restrict__ lo, int n4) {
    int i = blockIdx.x * blockDim.x + threadIdx.x;
    if (i >= n4) return;
    float4 v = *(const float4*)(x + i * 4);
    uint32_t h0, l0, h1, l1;
    split_pair(v.x, v.y, h0, l0);
    split_pair(v.z, v.w, h1, l1);
    *(uint2*)(hi + i * 4) = make_uint2(h0, h1);
    *(uint2*)(lo + i * 4) = make_uint2(l0, l1);
}

// ---------------- small utility kernels --------------------------------------
__global__ void zero_kernel(float* p, int n) {
    int i = blockIdx.x * blockDim.x + threadIdx.x;
    if (i < n) p[i] = 0.0f;
}
__global__ void copy_kernel(float* __restrict__ dst, const float* __restrict__ src, int n) {
    int i = blockIdx.x * blockDim.x + threadIdx.x;
    if (i < n) dst[i] = src[i];
}
__global__ void deg_kernel(const int* __restrict__ rel, float* __restrict__ deg) {
    int r = blockIdx.x * blockDim.x + threadIdx.x;
    if (r < N_REL) {
        atomicAdd(&deg[rel[2*r+0]], 1.0f);
        atomicAdd(&deg[N_OBJ + rel[2*r+1]], 1.0f);
    }
}
// new_o = of + 0.5*(a0/degS + a1/degO); also writes bf16 split of new_o
__global__ void update_o_kernel(const float* __restrict__ of, const float* __restrict__ a0,
                                const float* __restrict__ a1, const float* __restrict__ deg,
                                float* __restrict__ out, u16* __restrict__ oh,
                                u16* __restrict__ ol, int ncols, int total) {
    int i = blockIdx.x * blockDim.x + threadIdx.x;
    if (i >= total) return;
    int r = i / ncols;
    float v = of[i] + 0.5f * (a0[i] / (deg[r] + 1e-7f) + a1[i] / (deg[N_OBJ + r] + 1e-7f));
    out[i] = v;
    if (oh) {
        __nv_bfloat16 hb = __float2bfloat16(v);
        __nv_bfloat16 lb = __float2bfloat16(v - __bfloat162float(hb));
        oh[i] = *(u16*)&hb; ol[i] = *(u16*)&lb;
    }
}
// new_p = pf + 0.5*(f0[subj]+f1[obj])/(1+1e-7); also writes bf16 split
__global__ void update_p_kernel(const float* __restrict__ pf, const float* __restrict__ f0,
                                const float* __restrict__ f1, const int* __restrict__ rel,
                                float* __restrict__ out, u16* __restrict__ oh,
                                u16* __restrict__ ol, int ncols, int total) {
    int i = blockIdx.x * blockDim.x + threadIdx.x;
    if (i >= total) return;
    int r = i / ncols;
    int c = i - r * ncols;
    int s = rel[2*r+0];
    int o = rel[2*r+1];
    float v = pf[i] + 0.5f * (f0[(size_t)s * ncols + c] + f1[(size_t)o * ncols + c]) / (1.0f + 1e-7f);
    out[i] = v;
    if (oh) {
        __nv_bfloat16 hb = __float2bfloat16(v);
        __nv_bfloat16 lb = __float2bfloat16(v - __bfloat162float(hb));
        oh[i] = *(u16*)&hb; ol[i] = *(u16*)&lb;
    }
}

// ---------------- small GEMM: one row per block -------------------------------
__global__ void rowgemm_kernel(const float* __restrict__ A, const float* __restrict__ W,
                               const float* __restrict__ bias, int K, int N, int doRelu,
                               float* __restrict__ C,
                               const int* __restrict__ rel, int sel, float* __restrict__ sacc) {
    extern __shared__ float xs[];
    const int row = blockIdx.x;
    const float* arow = A + (size_t)row * K;
    for (int k = threadIdx.x; k < K; k += blockDim.x) xs[k] = arow[k];
    __syncthreads();
    const int col = threadIdx.x;
    if (col >= N) return;
    float acc = bias[col];
    #pragma unroll 4
    for (int k = 0; k < K; k++)
        acc = fmaf(xs[k], W[(size_t)k * N + col], acc);
    if (doRelu) acc = fmaxf(acc, 0.0f);
    if (sacc) {
        int t = rel[row * 2 + sel];
        atomicAdd(&sacc[(size_t)t * N + col], acc);
    } else {
        C[(size_t)row * N + col] = acc;
    }
}

// ---------------- host helpers --------------------------------------------------
static inline void launch_zero(float* p, int n) {
    zero_kernel<<<(n + 255) / 256, 256>>>(p, n);
}
static inline void launch_split(const float* x, u16* h, u16* l, int n) {
    split_kernel<<<(n / 4 + 255) / 256, 256>>>(x, h, l, n / 4);
}
static inline void launch_gemm(const u16* Ah, const u16* Al, const u16* Bh, const u16* Bl,
                               const float* b, int M, int K, int N, int relu,
                               float* C, u16* Ch, u16* Cl,
                               const int* rel, int sel, float* sacc) {
    dim3 grid(N / 128, M / 128);
    gemm_bf16p<<<grid, 256, SMEM_GEMM>>>(Ah, Al, Bh, Bl, b, M, K, N, relu,
                                         C, Ch, Cl, rel, sel, sacc);
}
static inline void launch_rowgemm(const float* A, const float* W, const float* b,
                                  int M, int K, int N, int relu,
                                  float* C, const int* rel, int sel, float* sacc) {
    int nt = ((N + 31) / 32) * 32;
    rowgemm_kernel<<<M, nt, K * (int)sizeof(float)>>>(A, W, b, K, N, relu, C, rel, sel, sacc);
}
template <typename T>
static inline T* sym(const void* s) {
    void* p = nullptr;
    cudaGetSymbolAddress(&p, s);
    return (T*)p;
}

extern "C" void kernel_launch(void* const* d_in, const int* in_sizes, int n_in,
                              void* d_out, int out_size) {
    const float* x_obj_raw  = (const float*)d_in[0];
    const float* x_pred_raw = (const float*)d_in[1];
    const int*   rel        = (const int*)  d_in[2];
    const float* oW1 = (const float*)d_in[3],  *ob1 = (const float*)d_in[4];
    const float* oW2 = (const float*)d_in[5],  *ob2 = (const float*)d_in[6];
    const float* rW1 = (const float*)d_in[7],  *rb1 = (const float*)d_in[8];
    const float* rW2 = (const float*)d_in[9],  *rb2 = (const float*)d_in[10];
    const float* Wcf = (const float*)d_in[11], *bcf = (const float*)d_in[12];
    const float* Wso = (const float*)d_in[13], *bso = (const float*)d_in[14];
    const float* Wsr = (const float*)d_in[15], *bsr = (const float*)d_in[16];
    const float* Woc = (const float*)d_in[17], *boc = (const float*)d_in[18];
    const float* Wpc = (const float*)d_in[19], *bpc = (const float*)d_in[20];
    float* out = (float*)d_out;

    cudaFuncSetAttribute(gemm_bf16p, cudaFuncAttributeMaxDynamicSharedMemorySize, SMEM_GEMM);

    float* pfA   = sym<float>(g_pfeatA);
    float* pfB   = sym<float>(g_pfeatB);
    float* ofA   = sym<float>(g_ofeatA);
    float* ofB   = sym<float>(g_ofeatB);
    float* fco0  = sym<float>(g_fco0);
    float* fco1  = sym<float>(g_fco1);
    float* acc0  = sym<float>(g_acc0);
    float* acc1  = sym<float>(g_acc1);
    float* osA   = sym<float>(g_osA);
    float* osB   = sym<float>(g_osB);
    float* psA   = sym<float>(g_psA);
    float* psB   = sym<float>(g_psB);
    float* sacc0 = sym<float>(g_sacc0);
    float* sacc1 = sym<float>(g_sacc1);
    float* fcs0  = sym<float>(g_fcs0);
    float* fcs1  = sym<float>(g_fcs1);
    float* deg   = sym<float>(g_deg);

    u16* xo_h = sym<u16>(g_xo_h),  *xo_l = sym<u16>(g_xo_l);
    u16* xp_h = sym<u16>(g_xp_h),  *xp_l = sym<u16>(g_xp_l);
    u16* hob_h = sym<u16>(g_hob_h), *hob_l = sym<u16>(g_hob_l);
    u16* hpr_h = sym<u16>(g_hpr_h), *hpr_l = sym<u16>(g_hpr_l);
    u16* pf_h = sym<u16>(g_pf_h),  *pf_l = sym<u16>(g_pf_l);
    u16* of_h[2] = { sym<u16>(g_of_h0), sym<u16>(g_of_h1) };
    u16* of_l[2] = { sym<u16>(g_of_l0), sym<u16>(g_of_l1) };
    u16* oW1h = sym<u16>(g_oW1h), *oW1l = sym<u16>(g_oW1l);
    u16* oW2h = sym<u16>(g_oW2h), *oW2l = sym<u16>(g_oW2l);
    u16* rW1h = sym<u16>(g_rW1h), *rW1l = sym<u16>(g_rW1l);
    u16* rW2h = sym<u16>(g_rW2h), *rW2l = sym<u16>(g_rW2l);
    u16* Wcfh = sym<u16>(g_Wcfh), *Wcfl = sym<u16>(g_Wcfl);

    // ---- degrees + operand conversion ----
    launch_zero(deg, 2 * N_OBJ);
    deg_kernel<<<(N_REL + 255) / 256, 256>>>(rel, deg);
    launch_split(x_obj_raw,  xo_h, xo_l, N_OBJ * FEAT);
    launch_split(x_pred_raw, xp_h, xp_l, N_REL * FEAT);
    launch_split(oW1, oW1h, oW1l, FEAT * DIM);
    launch_split(oW2, oW2h, oW2l, DIM * DIM);
    launch_split(rW1, rW1h, rW1l, FEAT * DIM);
    launch_split(rW2, rW2h, rW2l, DIM * DIM);
    launch_split(Wcf, Wcfh, Wcfl, 4 * DIM * DIM);

    // ---- embedding MLPs ----
    // obj layer1: relu -> split only (hobj)
    launch_gemm(xo_h, xo_l, oW1h, oW1l, ob1, N_OBJ, FEAT, DIM, 1,
                nullptr, hob_h, hob_l, nullptr, 0, nullptr);
    // obj layer2: f32 ofA + split of[0]
    launch_gemm(hob_h, hob_l, oW2h, oW2l, ob2, N_OBJ, DIM, DIM, 0,
                ofA, of_h[0], of_l[0], nullptr, 0, nullptr);
    // pred layer1: relu -> split only (hpred)
    launch_gemm(xp_h, xp_l, rW1h, rW1l, rb1, N_REL, FEAT, DIM, 1,
                nullptr, hpr_h, hpr_l, nullptr, 0, nullptr);
    // pred layer2: f32 -> out (output #0 = x_pred) + split pf
    launch_gemm(hpr_h, hpr_l, rW2h, rW2l, rb2, N_REL, DIM, DIM, 0,
                out, pf_h, pf_l, nullptr, 0, nullptr);

    // ---- feature-level aGCN (2 steps) ----
    float* of = ofA;  float* ofn = ofB;
    float* pf = out;  float* pfn = pfB;
    int cur = 0;
    for (int st = 0; st < 2; st++) {
        launch_zero(acc0, N_OBJ * DIM);
        launch_zero(acc1, N_OBJ * DIM);
        // relu(pf @ Wc0/1 + b) scattered by subj/obj (fused epilogue)
        launch_gemm(pf_h, pf_l, Wcfh + 0 * DIM * DIM, Wcfl + 0 * DIM * DIM, bcf + 0 * DIM,
                    N_REL, DIM, DIM, 1, nullptr, nullptr, nullptr, rel, 0, acc0);
        launch_gemm(pf_h, pf_l, Wcfh + 1 * DIM * DIM, Wcfl + 1 * DIM * DIM, bcf + 1 * DIM,
                    N_REL, DIM, DIM, 1, nullptr, nullptr, nullptr, rel, 1, acc1);
        // new of (f32 + split into the other slot)
        update_o_kernel<<<(N_OBJ * DIM + 255) / 256, 256>>>(
            of, acc0, acc1, deg, ofn, of_h[cur ^ 1], of_l[cur ^ 1], DIM, N_OBJ * DIM);
        // relu(of @ Wc2/3 + b) -> f32 gather sources (uses OLD of split)
        launch_gemm(of_h[cur], of_l[cur], Wcfh + 2 * DIM * DIM, Wcfl + 2 * DIM * DIM,
                    bcf + 2 * DIM, N_OBJ, DIM, DIM, 1, fco0, nullptr, nullptr,
                    nullptr, 0, nullptr);
        launch_gemm(of_h[cur], of_l[cur], Wcfh + 3 * DIM * DIM, Wcfl + 3 * DIM * DIM,
                    bcf + 3 * DIM, N_OBJ, DIM, DIM, 1, fco1, nullptr, nullptr,
                    nullptr, 0, nullptr);
        // new pf (f32 + split, overwrites pf split consumed above)
        update_p_kernel<<<(N_REL * DIM + 255) / 256, 256>>>(
            pf, fco0, fco1, rel, pfn, pf_h, pf_l, DIM, N_REL * DIM);
        float* t = of; of = ofn; ofn = t;
        pf = pfn; pfn = (st == 0) ? pfA : pfB;
        cur ^= 1;
    }

    // ---- classifiers ----
    launch_rowgemm(of, Woc, boc, N_OBJ, DIM, NC_OBJ,  0, osA, nullptr, 0, nullptr);
    launch_rowgemm(pf, Wpc, bpc, N_REL, DIM, NC_PRED, 0, psA, nullptr, 0, nullptr);

    // ---- score-level aGCN (2 steps) ----
    float* os = osA; float* osn = osB;
    float* ps = psA; float* psn = psB;
    for (int st = 0; st < 2; st++) {
        launch_zero(sacc0, N_OBJ * NC_OBJ);
        launch_zero(sacc1, N_OBJ * NC_OBJ);
        launch_rowgemm(ps, Wso + 0 * NC_PRED * NC_OBJ, bso + 0 * NC_OBJ,
                       N_REL, NC_PRED, NC_OBJ, 1, nullptr, rel, 0, sacc0);
        launch_rowgemm(ps, Wso + 1 * NC_PRED * NC_OBJ, bso + 1 * NC_OBJ,
                       N_REL, NC_PRED, NC_OBJ, 1, nullptr, rel, 1, sacc1);
        update_o_kernel<<<(N_OBJ * NC_OBJ + 255) / 256, 256>>>(
            os, sacc0, sacc1, deg, osn, nullptr, nullptr, NC_OBJ, N_OBJ * NC_OBJ);
        launch_rowgemm(os, Wsr + 0 * NC_OBJ * NC_PRED, bsr + 0 * NC_PRED,
                       N_OBJ, NC_OBJ, NC_PRED, 1, fcs0, nullptr, 0, nullptr);
        launch_rowgemm(os, Wsr + 1 * NC_OBJ * NC_PRED, bsr + 1 * NC_PRED,
                       N_OBJ, NC_OBJ, NC_PRED, 1, fcs1, nullptr, 0, nullptr);
        update_p_kernel<<<(N_REL * NC_PRED + 255) / 256, 256>>>(
            ps, fcs0, fcs1, rel, psn, nullptr, nullptr, NC_PRED, N_REL * NC_PRED);
        float* t;
        t = os; os = osn; osn = t;
        t = ps; ps = psn; psn = t;
    }

    // ---- outputs #1 and #2 ----
    copy_kernel<<<(N_OBJ * NC_OBJ + 255) / 256, 256>>>(out + (size_t)N_REL * DIM,
                                                       os, N_OBJ * NC_OBJ);
    copy_kernel<<<(N_REL * NC_PRED + 255) / 256, 256>>>(out + (size_t)N_REL * DIM + N_OBJ * NC_OBJ,
                                                        ps, N_REL * NC_PRED);
}

// round 5
// speedup vs baseline: 1.3280x; 1.3280x over previous
#include <cuda_runtime.h>
#include <cuda_fp16.h>
#include <cstdint>
#include <math.h>

#define N_OBJ   2048
#define N_REL   32768
#define FEAT    2048
#define DIM     512
#define NC_OBJ  151
#define NC_PRED 51

// ---------------- scratch (static device globals; no allocation) -------------
__device__ __align__(128) float g_hpred [N_REL*DIM];
__device__ __align__(128) float g_pfeatA[N_REL*DIM];
__device__ __align__(128) float g_pfeatB[N_REL*DIM];
__device__ __align__(128) float g_hobj  [N_OBJ*DIM];
__device__ __align__(128) float g_ofeatA[N_OBJ*DIM];
__device__ __align__(128) float g_ofeatB[N_OBJ*DIM];
__device__ __align__(128) float g_fco0  [N_OBJ*DIM];
__device__ __align__(128) float g_fco1  [N_OBJ*DIM];
__device__ __align__(128) float g_acc0  [N_OBJ*DIM];
__device__ __align__(128) float g_acc1  [N_OBJ*DIM];
__device__ __align__(128) float g_osA   [N_OBJ*NC_OBJ];
__device__ __align__(128) float g_osB   [N_OBJ*NC_OBJ];
__device__ __align__(128) float g_psA   [N_REL*NC_PRED];
__device__ __align__(128) float g_psB   [N_REL*NC_PRED];
__device__ __align__(128) float g_sacc0 [N_OBJ*NC_OBJ];
__device__ __align__(128) float g_sacc1 [N_OBJ*NC_OBJ];
__device__ __align__(128) float g_fcs0  [N_OBJ*NC_PRED];
__device__ __align__(128) float g_fcs1  [N_OBJ*NC_PRED];
__device__ __align__(128) float g_deg   [2*N_OBJ];

// ---------------- helpers ------------------------------------------------------
__device__ __forceinline__ uint32_t smem_u32(const void* p) {
    uint32_t a;
    asm("{ .reg .u64 t; cvta.to.shared.u64 t, %1; cvt.u32.u64 %0, t; }" : "=r"(a) : "l"(p));
    return a;
}
// pack fp16x2: lower16 = f16(x), upper16 = f16(y)  (same operand order convention
// as the bf16 version proven correct in R3)
__device__ __forceinline__ uint32_t pack_h2(float x, float y) {
    uint32_t d;
    asm("cvt.rn.f16x2.f32 %0, %1, %2;" : "=r"(d) : "f"(y), "f"(x));
    return d;
}
// split x,y into fp16 hi + fp16 lo (residual)
__device__ __forceinline__ void split_pair_h(float x, float y, uint32_t& hi, uint32_t& lo) {
    hi = pack_h2(x, y);
    __half2 h2 = *reinterpret_cast<const __half2*>(&hi);
    float fx = __low2float(h2);
    float fy = __high2float(h2);
    lo = pack_h2(x - fx, y - fy);
}
__device__ __forceinline__ void ldsm_x4(uint32_t* r, uint32_t addr) {
    asm volatile("ldmatrix.sync.aligned.m8n8.x4.shared.b16 {%0,%1,%2,%3}, [%4];"
                 : "=r"(r[0]), "=r"(r[1]), "=r"(r[2]), "=r"(r[3]) : "r"(addr));
}
__device__ __forceinline__ void ldsm_x4_t(uint32_t* r, uint32_t addr) {
    asm volatile("ldmatrix.sync.aligned.m8n8.x4.trans.shared.b16 {%0,%1,%2,%3}, [%4];"
                 : "=r"(r[0]), "=r"(r[1]), "=r"(r[2]), "=r"(r[3]) : "r"(addr));
}
__device__ __forceinline__ void mma16816(float* c, const uint32_t* a, uint32_t b0, uint32_t b1) {
    asm volatile("mma.sync.aligned.m16n8k16.row.col.f32.f16.f16.f32 "
                 "{%0,%1,%2,%3}, {%4,%5,%6,%7}, {%8,%9}, {%0,%1,%2,%3};"
                 : "+f"(c[0]), "+f"(c[1]), "+f"(c[2]), "+f"(c[3])
                 : "r"(a[0]), "r"(a[1]), "r"(a[2]), "r"(a[3]), "r"(b0), "r"(b1));
}

// ---------------- fp16-split tensor GEMM (2 passes: A_hi@B + A_lo@B) ----------
// C[M,N] = op(A[M,K] @ W[K,N] + bias),  M%128==0, N%128==0, K%32==0.
// A split into fp16 hi/lo (exact to 2^-22); B single fp16 (err ~1.4e-4).
// If sacc: relu'd value atomicAdd'ed to sacc[rel[r*2+sel]*N + c]; else stored to C.
#define APITCH 80    // bytes per A row (32 f16 = 64B + 16B pad)
#define BPITCH 272   // bytes per B row (128 f16 = 256B + 16B pad)
#define ST_AHI 0
#define ST_ALO 10240
#define ST_BHI 20480
#define ST_SZ  29184
#define SMEM_GEMM (2*ST_SZ)

__global__ __launch_bounds__(256)
void gemm_f16s(const float* __restrict__ A, const float* __restrict__ W,
               const float* __restrict__ bias, int M, int K, int N, int doRelu,
               float* __restrict__ C,
               const int* __restrict__ rel, int sel, float* __restrict__ sacc) {
    extern __shared__ __align__(128) char smem[];
    const uint32_t sb = smem_u32(smem);
    const int tid = threadIdx.x;
    const int lane = tid & 31;
    const int w = tid >> 5;
    const int warp_m = (w & 1) * 64;
    const int warp_n = (w >> 1) * 32;
    const int m0 = blockIdx.y * 128;
    const int n0 = blockIdx.x * 128;

    float acc[16][4];
    #pragma unroll
    for (int i = 0; i < 16; i++)
        #pragma unroll
        for (int j = 0; j < 4; j++) acc[i][j] = 0.0f;

    float4 ra[4], rb[4];

    auto ldg_tile = [&](int kt) {
        #pragma unroll
        for (int i = 0; i < 4; i++) {
            int f = (i * 256 + tid) * 4;
            ra[i] = *(const float4*)(A + (size_t)(m0 + (f >> 5)) * K + kt * 32 + (f & 31));
            rb[i] = *(const float4*)(W + (size_t)(kt * 32 + (f >> 7)) * N + n0 + (f & 127));
        }
    };
    auto sts_tile = [&](int s) {
        const uint32_t st = sb + s * ST_SZ;
        #pragma unroll
        for (int i = 0; i < 4; i++) {
            int f = (i * 256 + tid) * 4;
            {   // A: hi + lo
                uint32_t h0, l0, h1, l1;
                split_pair_h(ra[i].x, ra[i].y, h0, l0);
                split_pair_h(ra[i].z, ra[i].w, h1, l1);
                uint32_t off = (uint32_t)((f >> 5) * APITCH + (f & 31) * 2);
                asm volatile("st.shared.v2.b32 [%0], {%1,%2};" :: "r"(st + ST_AHI + off), "r"(h0), "r"(h1) : "memory");
                asm volatile("st.shared.v2.b32 [%0], {%1,%2};" :: "r"(st + ST_ALO + off), "r"(l0), "r"(l1) : "memory");
            }
            {   // B: hi only
                uint32_t h0 = pack_h2(rb[i].x, rb[i].y);
                uint32_t h1 = pack_h2(rb[i].z, rb[i].w);
                uint32_t off = (uint32_t)((f >> 7) * BPITCH + (f & 127) * 2);
                asm volatile("st.shared.v2.b32 [%0], {%1,%2};" :: "r"(st + ST_BHI + off), "r"(h0), "r"(h1) : "memory");
            }
        }
    };

    ldg_tile(0);
    sts_tile(0);
    __syncthreads();

    const int KT = K >> 5;
    for (int kt = 0; kt < KT; kt++) {
        const int s = kt & 1;
        if (kt + 1 < KT) ldg_tile(kt + 1);

        const uint32_t st = sb + s * ST_SZ;
        #pragma unroll
        for (int ks = 0; ks < 2; ks++) {
            uint32_t ah[4][4], al[4][4];
            const uint32_t a_off = (uint32_t)((warp_m + (lane & 15)) * APITCH
                                              + ks * 32 + (lane >> 4) * 16);
            #pragma unroll
            for (int mi = 0; mi < 4; mi++) {
                ldsm_x4(ah[mi], st + ST_AHI + a_off + mi * 16 * APITCH);
                ldsm_x4(al[mi], st + ST_ALO + a_off + mi * 16 * APITCH);
            }
            const uint32_t b_off = (uint32_t)((ks * 16 + (lane & 15)) * BPITCH
                                              + (warp_n + (lane >> 4) * 8) * 2);
            #pragma unroll
            for (int np = 0; np < 2; np++) {
                uint32_t bh[4];
                ldsm_x4_t(bh, st + ST_BHI + b_off + np * 32);
                #pragma unroll
                for (int mi = 0; mi < 4; mi++) {
                    #pragma unroll
                    for (int j = 0; j < 2; j++) {
                        float* c = acc[mi * 4 + np * 2 + j];
                        mma16816(c, ah[mi], bh[2*j], bh[2*j+1]);
                        mma16816(c, al[mi], bh[2*j], bh[2*j+1]);
                    }
                }
            }
        }

        if (kt + 1 < KT) sts_tile(s ^ 1);
        __syncthreads();
    }

    // ---- epilogue ----
    const int g = lane >> 2, tig = lane & 3;
    #pragma unroll
    for (int mi = 0; mi < 4; mi++) {
        const int r0 = m0 + warp_m + mi * 16 + g;
        const int r1 = r0 + 8;
        int t0 = 0, t1 = 0;
        if (sacc) { t0 = rel[r0 * 2 + sel]; t1 = rel[r1 * 2 + sel]; }
        #pragma unroll
        for (int ni = 0; ni < 4; ni++) {
            const int c = n0 + warp_n + ni * 8 + tig * 2;
            float b0 = bias[c], b1 = bias[c + 1];
            float* a = acc[mi * 4 + ni];
            float v0 = a[0] + b0, v1 = a[1] + b1, v2 = a[2] + b0, v3 = a[3] + b1;
            if (doRelu) {
                v0 = fmaxf(v0, 0.0f); v1 = fmaxf(v1, 0.0f);
                v2 = fmaxf(v2, 0.0f); v3 = fmaxf(v3, 0.0f);
            }
            if (sacc) {
                atomicAdd(&sacc[(size_t)t0 * N + c],     v0);
                atomicAdd(&sacc[(size_t)t0 * N + c + 1], v1);
                atomicAdd(&sacc[(size_t)t1 * N + c],     v2);
                atomicAdd(&sacc[(size_t)t1 * N + c + 1], v3);
            } else {
                *(float2*)(C + (size_t)r0 * N + c) = make_float2(v0, v1);
                *(float2*)(C + (size_t)r1 * N + c) = make_float2(v2, v3);
            }
        }
    }
}

// ---------------- tiled small GEMM: W cached in smem, 32 rows/block -----------
// fp32 exact. NPAD: thread->col mapping width; RPT: rows per thread (32*NPAD/256... )
// block = 256 threads = (256/NPAD) row-partitions x NPAD cols. WG_RB = 32 rows.
template<int NPAD, int RPT>
__global__ __launch_bounds__(256)
void wgemm_t(const float* __restrict__ A, const float* __restrict__ W,
             const float* __restrict__ bias, int K, int N, int KC, int doRelu,
             float* __restrict__ C,
             const int* __restrict__ rel, int sel, float* __restrict__ sacc) {
    extern __shared__ float sh[];
    float* Ws = sh;                       // [KC][N] contiguous
    float* As = sh + (size_t)KC * N;      // [32][KC]
    const int tid = threadIdx.x;
    const int col = tid % NPAD;
    const int part = tid / NPAD;
    const int rbase = part * RPT;
    const int row0 = blockIdx.x * 32;
    const bool active = col < N;

    float acc[RPT];
    float b = active ? bias[col] : 0.0f;
    #pragma unroll
    for (int r = 0; r < RPT; r++) acc[r] = b;

    for (int k0 = 0; k0 < K; k0 += KC) {
        const int kc = (K - k0 < KC) ? (K - k0) : KC;
        // W chunk is contiguous in global: [k0*N, (k0+kc)*N)
        for (int i = tid; i < kc * N; i += 256)
            Ws[i] = W[(size_t)k0 * N + i];
        for (int i = tid; i < 32 * kc; i += 256) {
            int rr = i / kc, kk = i - rr * kc;
            As[rr * KC + kk] = A[(size_t)(row0 + rr) * K + k0 + kk];
        }
        __syncthreads();
        if (active) {
            for (int k = 0; k < kc; k++) {
                float wv = Ws[k * N + col];
                #pragma unroll
                for (int r = 0; r < RPT; r++)
                    acc[r] = fmaf(As[(rbase + r) * KC + k], wv, acc[r]);
            }
        }
        __syncthreads();
    }

    if (active) {
        #pragma unroll
        for (int r = 0; r < RPT; r++) {
            int row = row0 + rbase + r;
            float v = acc[r];
            if (doRelu) v = fmaxf(v, 0.0f);
            if (sacc) {
                int t = rel[row * 2 + sel];
                atomicAdd(&sacc[(size_t)t * N + col], v);
            } else {
                C[(size_t)row * N + col] = v;
            }
        }
    }
}

// ---------------- small utility kernels --------------------------------------
__global__ void zero_kernel(float* p, int n) {
    int i = blockIdx.x * blockDim.x + threadIdx.x;
    if (i < n) p[i] = 0.0f;
}
__global__ void copy_kernel(float* __restrict__ dst, const float* __restrict__ src, int n) {
    int i = blockIdx.x * blockDim.x + threadIdx.x;
    if (i < n) dst[i] = src[i];
}
__global__ void deg_kernel(const int* __restrict__ rel, float* __restrict__ deg) {
    int r = blockIdx.x * blockDim.x + threadIdx.x;
    if (r < N_REL) {
        atomicAdd(&deg[rel[2*r+0]], 1.0f);
        atomicAdd(&deg[N_OBJ + rel[2*r+1]], 1.0f);
    }
}
__global__ void update_o_kernel(const float* __restrict__ of, const float* __restrict__ a0,
                                const float* __restrict__ a1, const float* __restrict__ deg,
                                float* __restrict__ out, int ncols, int total) {
    int i = blockIdx.x * blockDim.x + threadIdx.x;
    if (i >= total) return;
    int r = i / ncols;
    out[i] = of[i] + 0.5f * (a0[i] / (deg[r] + 1e-7f) + a1[i] / (deg[N_OBJ + r] + 1e-7f));
}
__global__ void update_p_kernel(const float* __restrict__ pf, const float* __restrict__ f0,
                                const float* __restrict__ f1, const int* __restrict__ rel,
                                float* __restrict__ out, int ncols, int total) {
    int i = blockIdx.x * blockDim.x + threadIdx.x;
    if (i >= total) return;
    int r = i / ncols;
    int c = i - r * ncols;
    int s = rel[2*r+0];
    int o = rel[2*r+1];
    out[i] = pf[i] + 0.5f * (f0[(size_t)s * ncols + c] + f1[(size_t)o * ncols + c]) / (1.0f + 1e-7f);
}

// ---------------- host launch helpers -----------------------------------------
static inline void launch_zero(float* p, int n) {
    zero_kernel<<<(n + 255) / 256, 256>>>(p, n);
}
static inline void launch_gemm(const float* A, const float* W, const float* b,
                               int M, int K, int N, int relu,
                               float* C, const int* rel, int sel, float* sacc) {
    dim3 grid(N / 128, M / 128);
    gemm_f16s<<<grid, 256, SMEM_GEMM>>>(A, W, b, M, K, N, relu, C, rel, sel, sacc);
}
static inline void launch_wgemm(const float* A, const float* W, const float* b,
                                int M, int K, int N, int relu,
                                float* C, const int* rel, int sel, float* sacc) {
    int KC = K;
    size_t bytes = ((size_t)KC * N + 32 * KC) * 4;
    if (bytes > 190 * 1024) {
        KC = 256;
        bytes = ((size_t)KC * N + 32 * KC) * 4;
    }
    if (N <= 64)
        wgemm_t<64, 8><<<M / 32, 256, bytes>>>(A, W, b, K, N, KC, relu, C, rel, sel, sacc);
    else
        wgemm_t<256, 32><<<M / 32, 256, bytes>>>(A, W, b, K, N, KC, relu, C, rel, sel, sacc);
}
template <typename T>
static inline T* sym(const void* s) {
    void* p = nullptr;
    cudaGetSymbolAddress(&p, s);
    return (T*)p;
}

extern "C" void kernel_launch(void* const* d_in, const int* in_sizes, int n_in,
                              void* d_out, int out_size) {
    const float* x_obj_raw  = (const float*)d_in[0];
    const float* x_pred_raw = (const float*)d_in[1];
    const int*   rel        = (const int*)  d_in[2];
    const float* oW1 = (const float*)d_in[3],  *ob1 = (const float*)d_in[4];
    const float* oW2 = (const float*)d_in[5],  *ob2 = (const float*)d_in[6];
    const float* rW1 = (const float*)d_in[7],  *rb1 = (const float*)d_in[8];
    const float* rW2 = (const float*)d_in[9],  *rb2 = (const float*)d_in[10];
    const float* Wcf = (const float*)d_in[11], *bcf = (const float*)d_in[12];
    const float* Wso = (const float*)d_in[13], *bso = (const float*)d_in[14];
    const float* Wsr = (const float*)d_in[15], *bsr = (const float*)d_in[16];
    const float* Woc = (const float*)d_in[17], *boc = (const float*)d_in[18];
    const float* Wpc = (const float*)d_in[19], *bpc = (const float*)d_in[20];
    float* out = (float*)d_out;

    // host-side, idempotent: safe under graph capture
    cudaFuncSetAttribute(gemm_f16s, cudaFuncAttributeMaxDynamicSharedMemorySize, SMEM_GEMM);
    cudaFuncSetAttribute(wgemm_t<64, 8>,   cudaFuncAttributeMaxDynamicSharedMemorySize, 195 * 1024);
    cudaFuncSetAttribute(wgemm_t<256, 32>, cudaFuncAttributeMaxDynamicSharedMemorySize, 195 * 1024);

    float* hpred = sym<float>(g_hpred);
    float* pfA   = sym<float>(g_pfeatA);
    float* pfB   = sym<float>(g_pfeatB);
    float* hobj  = sym<float>(g_hobj);
    float* ofA   = sym<float>(g_ofeatA);
    float* ofB   = sym<float>(g_ofeatB);
    float* fco0  = sym<float>(g_fco0);
    float* fco1  = sym<float>(g_fco1);
    float* acc0  = sym<float>(g_acc0);
    float* acc1  = sym<float>(g_acc1);
    float* osA   = sym<float>(g_osA);
    float* osB   = sym<float>(g_osB);
    float* psA   = sym<float>(g_psA);
    float* psB   = sym<float>(g_psB);
    float* sacc0 = sym<float>(g_sacc0);
    float* sacc1 = sym<float>(g_sacc1);
    float* fcs0  = sym<float>(g_fcs0);
    float* fcs1  = sym<float>(g_fcs1);
    float* deg   = sym<float>(g_deg);

    // ---- degrees ----
    launch_zero(deg, 2 * N_OBJ);
    deg_kernel<<<(N_REL + 255) / 256, 256>>>(rel, deg);

    // ---- embedding MLPs ----
    launch_gemm(x_obj_raw, oW1, ob1, N_OBJ, FEAT, DIM, 1, hobj, nullptr, 0, nullptr);
    launch_gemm(hobj,      oW2, ob2, N_OBJ, DIM,  DIM, 0, ofA,  nullptr, 0, nullptr);
    launch_gemm(x_pred_raw, rW1, rb1, N_REL, FEAT, DIM, 1, hpred, nullptr, 0, nullptr);
    // pred MLP layer 2 writes x_pred directly into out (output #0)
    launch_gemm(hpred,      rW2, rb2, N_REL, DIM,  DIM, 0, out,   nullptr, 0, nullptr);

    // ---- feature-level aGCN (2 steps) ----
    float* of = ofA;  float* ofn = ofB;
    float* pf = out;  float* pfn = pfB;
    for (int st = 0; st < 2; st++) {
        launch_zero(acc0, N_OBJ * DIM);
        launch_zero(acc1, N_OBJ * DIM);
        launch_gemm(pf, Wcf + 0 * DIM * DIM, bcf + 0 * DIM, N_REL, DIM, DIM, 1,
                    nullptr, rel, 0, acc0);
        launch_gemm(pf, Wcf + 1 * DIM * DIM, bcf + 1 * DIM, N_REL, DIM, DIM, 1,
                    nullptr, rel, 1, acc1);
        update_o_kernel<<<(N_OBJ * DIM + 255) / 256, 256>>>(of, acc0, acc1, deg, ofn,
                                                            DIM, N_OBJ * DIM);
        launch_gemm(of, Wcf + 2 * DIM * DIM, bcf + 2 * DIM, N_OBJ, DIM, DIM, 1,
                    fco0, nullptr, 0, nullptr);
        launch_gemm(of, Wcf + 3 * DIM * DIM, bcf + 3 * DIM, N_OBJ, DIM, DIM, 1,
                    fco1, nullptr, 0, nullptr);
        update_p_kernel<<<(N_REL * DIM + 255) / 256, 256>>>(pf, fco0, fco1, rel, pfn,
                                                            DIM, N_REL * DIM);
        float* t = of; of = ofn; ofn = t;
        pf = pfn; pfn = (st == 0) ? pfA : pfB;
    }

    // ---- classifiers (exact fp32, W cached in smem) ----
    launch_wgemm(of, Woc, boc, N_OBJ, DIM, NC_OBJ,  0, osA, nullptr, 0, nullptr);
    launch_wgemm(pf, Wpc, bpc, N_REL, DIM, NC_PRED, 0, psA, nullptr, 0, nullptr);

    // ---- score-level aGCN (2 steps) ----
    float* os = osA; float* osn = osB;
    float* ps = psA; float* psn = psB;
    for (int st = 0; st < 2; st++) {
        launch_zero(sacc0, N_OBJ * NC_OBJ);
        launch_zero(sacc1, N_OBJ * NC_OBJ);
        launch_wgemm(ps, Wso + 0 * NC_PRED * NC_OBJ, bso + 0 * NC_OBJ,
                     N_REL, NC_PRED, NC_OBJ, 1, nullptr, rel, 0, sacc0);
        launch_wgemm(ps, Wso + 1 * NC_PRED * NC_OBJ, bso + 1 * NC_OBJ,
                     N_REL, NC_PRED, NC_OBJ, 1, nullptr, rel, 1, sacc1);
        update_o_kernel<<<(N_OBJ * NC_OBJ + 255) / 256, 256>>>(os, sacc0, sacc1, deg, osn,
                                                               NC_OBJ, N_OBJ * NC_OBJ);
        launch_wgemm(os, Wsr + 0 * NC_OBJ * NC_PRED, bsr + 0 * NC_PRED,
                     N_OBJ, NC_OBJ, NC_PRED, 1, fcs0, nullptr, 0, nullptr);
        launch_wgemm(os, Wsr + 1 * NC_OBJ * NC_PRED, bsr + 1 * NC_PRED,
                     N_OBJ, NC_OBJ, NC_PRED, 1, fcs1, nullptr, 0, nullptr);
        update_p_kernel<<<(N_REL * NC_PRED + 255) / 256, 256>>>(ps, fcs0, fcs1, rel, psn,
                                                                NC_PRED, N_REL * NC_PRED);
        float* t;
        t = os; os = osn; osn = t;
        t = ps; ps = psn; psn = t;
    }

    // ---- outputs #1 and #2 ----
    copy_kernel<<<(N_OBJ * NC_OBJ + 255) / 256, 256>>>(out + (size_t)N_REL * DIM,
                                                       os, N_OBJ * NC_OBJ);
    copy_kernel<<<(N_REL * NC_PRED + 255) / 256, 256>>>(out + (size_t)N_REL * DIM + N_OBJ * NC_OBJ,
                                                        ps, N_REL * NC_PRED);
}